// round 14
// baseline (speedup 1.0000x reference)
#include <cuda_runtime.h>
#include <cuda_bf16.h>
#include <cstdint>

// Problem dims
#define TT 2048
#define BB 64
#define FFD 256
#define HH 256
#define NG 768  // 3*H

// Recurrence config: 16 clusters x 8 CTAs, 256 threads
#define CSZ 8
#define NCTA 128
#define NT 256

// -------- device scratch --------
__device__ float g_dump[(size_t)TT * BB * HH];   // fallback ys sink

// -------- packed f32x2 helpers --------
__device__ __forceinline__ void ffma2(unsigned long long& d, unsigned long long a, unsigned long long b) {
    asm volatile("fma.rn.f32x2 %0, %1, %2, %0;" : "+l"(d) : "l"(a), "l"(b));
}
__device__ __forceinline__ void add2(unsigned long long& d, unsigned long long a) {
    asm volatile("add.rn.f32x2 %0, %0, %1;" : "+l"(d) : "l"(a));
}
__device__ __forceinline__ unsigned long long dup2(float a) {
    unsigned long long d;
    asm("mov.b64 %0, {%1, %1};" : "=l"(d) : "f"(a));
    return d;
}
__device__ __forceinline__ unsigned long long pack2(float a, float b) {
    unsigned long long d;
    asm("mov.b64 %0, {%1, %2};" : "=l"(d) : "f"(a), "f"(b));
    return d;
}
__device__ __forceinline__ float2 unpack2(unsigned long long d) {
    float2 f;
    asm("mov.b64 {%0, %1}, %2;" : "=f"(f.x), "=f"(f.y) : "l"(d));
    return f;
}
__device__ __forceinline__ float tanh_ap(float x) {
    float y;
    asm("tanh.approx.f32 %0, %1;" : "=f"(y) : "f"(x));
    return y;
}
__device__ __forceinline__ float sigmoid_ap(float x) {
    return 0.5f * tanh_ap(0.5f * x) + 0.5f;
}
__device__ __forceinline__ uint32_t smem_u32(const void* p) {
    uint32_t a;
    asm("{ .reg .u64 t; cvta.to.shared.u64 t, %1; cvt.u32.u64 %0, t; }" : "=r"(a) : "l"(p));
    return a;
}
// CTA-scope wait: no cluster-scope acquire -> no CCTL.IVALL on the poll loop.
__device__ __forceinline__ void mbar_wait_cta(uint32_t mbar, unsigned parity) {
    asm volatile(
        "{\n\t.reg .pred p;\n\t"
        "WAIT_%=:\n\t"
        "mbarrier.try_wait.parity.acquire.cta.shared::cta.b64 p, [%0], %1, 0x989680;\n\t"
        "@!p bra WAIT_%=;\n\t}"
        :: "r"(mbar), "r"(parity) : "memory");
}
// Remote tx-tracked store: data + completion bytes to peer CTA (R7-proven .b32)
__device__ __forceinline__ void st_async_f32(uint32_t daddr, float v, uint32_t maddr) {
    asm volatile(
        "st.async.shared::cluster.mbarrier::complete_tx::bytes.b32 [%0], %1, [%2];"
        :: "r"(daddr), "r"(__float_as_uint(v)), "r"(maddr) : "memory");
}

// ============================================================
// Single persistent kernel: clustered GRU recurrence with FUSED
// xi = xs @ Wi production in the idle warps (tid 128..255).
//
// - Wh slice in registers (R7); Wi slice [256k][96c] in smem
// - xi[t+2] computed at step t by warps 4..7 during the gates/wait slack
//   (phase-1-style GEMV + bar.sync(1,128) reduce -> xiF 4-slot ring)
// - xs[t+3] staged (dup'd f32x2) into a 4-slot smem ring
// - sync/exchange protocol: EXACTLY R7 (monolithic per-buffer mbarrier,
//   scalar .b32 st.async x 8 ranks, expect_tx/acquire.cta ping-pong)
// ============================================================

// smem float offsets
#define OFF_RED  0       // [256][36] Wh partials -> 9216
#define OFF_HT   9216    // [2][256 k][4 b] h (non-dup) -> 11264
#define OFF_MB   11264   // 2 mbarriers (+pad) -> 11272
#define OFF_XIF  11272   // [4 slots][4 b][96] xi finals -> 12808
#define OFF_RED2 12808   // [128][26] xi partials -> 16136
#define OFF_XS   16136   // [4 slots][256 k][4 b dup f32x2] -> 24328
#define OFF_WI   24328   // [256 k][96+2] Wi slice -> 49416
#define SMEM_FLOATS 49416
#define SMEM_BYTES (SMEM_FLOATS * 4)   // 197664 B -> attr REQUIRED

#define TX_BYTES 4096u   // 8 ranks x 64 threads x 2 f32 x 4B into each CTA

// xi GEMV + reduce for one (xs_slot -> xif_slot); u = tid-128 in [0,128)
__device__ __forceinline__ void xi_compute(float* sm, int u, int xs_slot, int xif_slot) {
    float* sWi = sm + OFF_WI;
    float* sXS = sm + OFF_XS + xs_slot * 2048;
    float* sR2 = sm + OFF_RED2;
    float* sXF = sm + OFF_XIF + xif_slot * 384;
    const int kc = u >> 4;   // 0..7, 32 k each
    const int jp = u & 15;   // j-pair 0..15

    unsigned long long acc[3][4];
#pragma unroll
    for (int g = 0; g < 3; g++)
#pragma unroll
        for (int b = 0; b < 4; b++) acc[g][b] = 0ULL;

#pragma unroll 8
    for (int kk = 0; kk < 32; kk++) {
        int k = kc * 32 + kk;
        ulonglong2 hA = *(const ulonglong2*)(sXS + k * 8);      // dup(b0), dup(b1)
        ulonglong2 hB = *(const ulonglong2*)(sXS + k * 8 + 4);  // dup(b2), dup(b3)
        const float* wr = sWi + k * 98 + 2 * jp;
        unsigned long long w0 = *(const unsigned long long*)(wr);
        unsigned long long w1 = *(const unsigned long long*)(wr + 32);
        unsigned long long w2 = *(const unsigned long long*)(wr + 64);
        ffma2(acc[0][0], w0, hA.x); ffma2(acc[0][1], w0, hA.y);
        ffma2(acc[0][2], w0, hB.x); ffma2(acc[0][3], w0, hB.y);
        ffma2(acc[1][0], w1, hA.x); ffma2(acc[1][1], w1, hA.y);
        ffma2(acc[1][2], w1, hB.x); ffma2(acc[1][3], w1, hB.y);
        ffma2(acc[2][0], w2, hA.x); ffma2(acc[2][1], w2, hA.y);
        ffma2(acc[2][2], w2, hB.x); ffma2(acc[2][3], w2, hB.y);
    }
    {
        float* rp = sR2 + u * 26;
#pragma unroll
        for (int b = 0; b < 4; b++) {
            *(unsigned long long*)(rp + b * 6 + 0) = acc[0][b];
            *(unsigned long long*)(rp + b * 6 + 2) = acc[1][b];
            *(unsigned long long*)(rp + b * 6 + 4) = acc[2][b];
        }
    }
    asm volatile("bar.sync 1, 128;" ::: "memory");
    // reduce: this thread = (b2, jl)
    {
        int b2 = u >> 5, jl = u & 31, jpr = jl >> 1, hf = jl & 1;
#pragma unroll
        for (int g = 0; g < 3; g++) {
            float s = 0.f;
#pragma unroll
            for (int q = 0; q < 8; q++)
                s += sR2[(q * 16 + jpr) * 26 + b2 * 6 + g * 2 + hf];
            sXF[b2 * 96 + g * 32 + jl] = s;
        }
    }
}

__global__ __launch_bounds__(NT, 1) __cluster_dims__(CSZ, 1, 1)
void gru_rec_kernel(const float* __restrict__ c,
                    const float* __restrict__ xs,
                    const float* __restrict__ Wi,
                    const float* __restrict__ Wh,
                    const float* __restrict__ bh,
                    const float* __restrict__ b_in,
                    float* __restrict__ ys,
                    float* __restrict__ finalc) {
    extern __shared__ float sm[];
    float* sRED = sm + OFF_RED;
    float* sHT  = sm + OFF_HT;
    float* sXIF = sm + OFF_XIF;

    const int tid = threadIdx.x;
    uint32_t rank;
    asm("mov.u32 %0, %%cluster_ctarank;" : "=r"(rank));
    const int cid = blockIdx.x >> 3;          // cluster id 0..15 (batches 4cid..+3)

    const uint32_t mbase = smem_u32(sm + OFF_MB);

    // ---- init mbarriers (count = 1: the local expect_tx arrival) ----
    if (tid == 0) {
        asm volatile("mbarrier.init.shared.b64 [%0], %1;" :: "r"(mbase), "r"(1u) : "memory");
        asm volatile("mbarrier.init.shared.b64 [%0], %1;" :: "r"(mbase + 8), "r"(1u) : "memory");
        asm volatile("mbarrier.arrive.expect_tx.shared.b64 _, [%0], %1;"
                     :: "r"(mbase + 8), "r"(TX_BYTES) : "memory");
    }

    // ---- phase-1 mapping + Wh load into registers ----
    const int kc = tid >> 4;       // k-chunk 0..15 (16 k each)
    const int jp = tid & 15;       // j-pair 0..15
    const int j0w = (int)rank * 32 + jp * 2;

    unsigned long long wreg[48];
#pragma unroll
    for (int kk = 0; kk < 16; kk++) {
#pragma unroll
        for (int g = 0; g < 3; g++) {
            float2 w2 = __ldg((const float2*)(Wh + (size_t)(kc * 16 + kk) * 768 + g * 256 + j0w));
            wreg[kk * 3 + g] = pack2(w2.x, w2.y);
        }
    }

    // Wi slice -> smem [k][96+2]: cc = g*32+jl -> Wi col g*256 + rank*32 + jl
    for (int idx = tid; idx < 256 * 96; idx += NT) {
        int k = idx / 96;
        int cc = idx - k * 96;
        int g = cc >> 5;
        int jl = cc & 31;
        sm[OFF_WI + k * 98 + cc] = __ldg(Wi + (size_t)k * 768 + g * 256 + (int)rank * 32 + jl);
    }

    // initial h into buf 0: sHT[0][k][b] = c[cid*4+b][k]
    for (int idx = tid; idx < 1024; idx += NT) {
        int k = idx >> 2;
        int b = idx & 3;
        sHT[k * 4 + b] = __ldg(c + (size_t)(cid * 4 + b) * 256 + k);
    }

    // gate mapping (tid < 64)
    const int jp_g = tid & 15;
    const int b_g = tid >> 4;                    // 0..3
    const int j0 = (int)rank * 32 + jp_g * 2;    // global j (even)
    const int b_glob = cid * 4 + (b_g & 3);

    float2 bhr2 = make_float2(0.f, 0.f), bhz2 = bhr2, bhn2 = bhr2, bin2 = bhr2;
    if (tid < 64) {
        bhr2 = __ldg((const float2*)(bh + j0));
        bhz2 = __ldg((const float2*)(bh + 256 + j0));
        bhn2 = __ldg((const float2*)(bh + 512 + j0));
        bin2 = __ldg((const float2*)(b_in + j0));
    }

    // remote addresses for all 8 ranks
    uint32_t ht_local = smem_u32(sHT);
    uint32_t rdata[CSZ], rmb0[CSZ], rmb1[CSZ];
#pragma unroll
    for (int r = 0; r < CSZ; r++) {
        asm("mapa.shared::cluster.u32 %0, %1, %2;" : "=r"(rdata[r]) : "r"(ht_local), "r"(r));
        asm("mapa.shared::cluster.u32 %0, %1, %2;" : "=r"(rmb0[r]) : "r"(mbase), "r"(r));
        asm("mapa.shared::cluster.u32 %0, %1, %2;" : "=r"(rmb1[r]) : "r"(mbase + 8u), "r"(r));
    }

    // ---- xi prologue: stage xs[0..2], compute xiF[0], xiF[1] ----
    const int u = tid - 128;
    if (tid >= 128) {
        // stage slots 0..2 (thread u: b = u&3, kk = u>>2)
        int sb = u & 3, skk = u >> 2;
#pragma unroll
        for (int s = 0; s < 3; s++) {
            const float* src = xs + ((size_t)s * 64 + cid * 4 + sb) * 256 + skk * 8;
            float4 v0 = __ldg((const float4*)src);
            float4 v1 = __ldg((const float4*)(src + 4));
            float* dst = sm + OFF_XS + s * 2048;
            int k0 = skk * 8;
            *(unsigned long long*)(dst + (k0 + 0) * 8 + sb * 2) = dup2(v0.x);
            *(unsigned long long*)(dst + (k0 + 1) * 8 + sb * 2) = dup2(v0.y);
            *(unsigned long long*)(dst + (k0 + 2) * 8 + sb * 2) = dup2(v0.z);
            *(unsigned long long*)(dst + (k0 + 3) * 8 + sb * 2) = dup2(v0.w);
            *(unsigned long long*)(dst + (k0 + 4) * 8 + sb * 2) = dup2(v1.x);
            *(unsigned long long*)(dst + (k0 + 5) * 8 + sb * 2) = dup2(v1.y);
            *(unsigned long long*)(dst + (k0 + 6) * 8 + sb * 2) = dup2(v1.z);
            *(unsigned long long*)(dst + (k0 + 7) * 8 + sb * 2) = dup2(v1.w);
        }
        asm volatile("bar.sync 1, 128;" ::: "memory");   // Wi load done by... (see below)
    }
    __syncthreads();   // Wi smem + xs slots + h buf0 all visible CTA-wide
    if (tid >= 128) {
        xi_compute(sm, u, 0, 0);
        asm volatile("bar.sync 1, 128;" ::: "memory");
        xi_compute(sm, u, 1, 1);
    }
    __syncthreads();
    // all CTAs' mbarriers + buffers ready before any peer traffic
    asm volatile("barrier.cluster.arrive.aligned;" ::: "memory");
    asm volatile("barrier.cluster.wait.aligned;" ::: "memory");

    unsigned ph0 = 0, ph1 = 0;
    int cur = 0;
    for (int t = 0; t < TT; t++) {
        const int nxt = cur ^ 1;

        // -- phase 1: register-weight GEMV partials (all 256 threads) --
        unsigned long long acc[3][4];
#pragma unroll
        for (int g = 0; g < 3; g++)
#pragma unroll
            for (int b = 0; b < 4; b++) acc[g][b] = 0ULL;
        {
            const float* hb = sHT + cur * 1024 + kc * 64;
#pragma unroll
            for (int kk = 0; kk < 16; kk++) {
                float4 h4 = *(const float4*)(hb + kk * 4);
                unsigned long long d0 = dup2(h4.x);
                unsigned long long d1 = dup2(h4.y);
                unsigned long long d2 = dup2(h4.z);
                unsigned long long d3 = dup2(h4.w);
                unsigned long long w0 = wreg[kk * 3 + 0];
                unsigned long long w1 = wreg[kk * 3 + 1];
                unsigned long long w2 = wreg[kk * 3 + 2];
                ffma2(acc[0][0], w0, d0); ffma2(acc[0][1], w0, d1);
                ffma2(acc[0][2], w0, d2); ffma2(acc[0][3], w0, d3);
                ffma2(acc[1][0], w1, d0); ffma2(acc[1][1], w1, d1);
                ffma2(acc[1][2], w1, d2); ffma2(acc[1][3], w1, d3);
                ffma2(acc[2][0], w2, d0); ffma2(acc[2][1], w2, d1);
                ffma2(acc[2][2], w2, d2); ffma2(acc[2][3], w2, d3);
            }
        }
        {
            float* rp = sRED + tid * 36;
#pragma unroll
            for (int b = 0; b < 4; b++) {
                ulonglong2 v;
                v.x = acc[0][b];
                v.y = acc[1][b];
                *(ulonglong2*)(rp + b * 8) = v;
                *(unsigned long long*)(rp + b * 8 + 4) = acc[2][b];
            }
        }
        __syncthreads();   // sync1

        // post expect_tx for the exchange at step t+1 (uses mb[cur])
        if (tid == 64 && t + 2 < TT) {
            uint32_t mb = mbase + (uint32_t)cur * 8u;
            asm volatile("mbarrier.arrive.expect_tx.shared.b64 _, [%0], %1;"
                         :: "r"(mb), "r"(TX_BYTES) : "memory");
        }

        // -- gate warps: reduce + gates + sends (tid < 64) --
        if (tid < 64) {
            unsigned long long r2 = 0ULL, z2 = 0ULL, n2 = 0ULL;
            const float* rp0 = sRED + jp_g * 36 + b_g * 8;
#pragma unroll
            for (int q = 0; q < 16; q++) {
                const float* p = rp0 + q * (16 * 36);
                ulonglong2 v = *(const ulonglong2*)p;
                unsigned long long v2 = *(const unsigned long long*)(p + 4);
                add2(r2, v.x);
                add2(z2, v.y);
                add2(n2, v2);
            }
            float2 hr = unpack2(r2), hz = unpack2(z2), hn = unpack2(n2);
            float ho0 = sHT[cur * 1024 + j0 * 4 + b_g];
            float ho1 = sHT[cur * 1024 + (j0 + 1) * 4 + b_g];

            // xi from smem ring (computed 2 steps ago)
            const float* xf = sXIF + (t & 3) * 384 + b_g * 96 + 2 * jp_g;
            float2 xr2 = *(const float2*)(xf);
            float2 xz2 = *(const float2*)(xf + 32);
            float2 xn2 = *(const float2*)(xf + 64);

            float r0 = sigmoid_ap(xr2.x + hr.x + bhr2.x);
            float r1 = sigmoid_ap(xr2.y + hr.y + bhr2.y);
            float z0 = sigmoid_ap(xz2.x + hz.x + bhz2.x);
            float z1 = sigmoid_ap(xz2.y + hz.y + bhz2.y);
            float n0 = tanh_ap(xn2.x + bin2.x + r0 * (hn.x + bhn2.x));
            float n1 = tanh_ap(xn2.y + bin2.y + r1 * (hn.y + bhn2.y));
            float h_new0 = (1.0f - z0) * n0 + z0 * ho0;
            float h_new1 = (1.0f - z1) * n1 + z1 * ho1;

            *(float2*)&ys[((size_t)t * 64 + b_glob) * 256 + j0] = make_float2(h_new0, h_new1);
            if (t == TT - 1)
                *(float2*)&finalc[(size_t)b_glob * 256 + j0] = make_float2(h_new0, h_new1);

            if (t + 1 < TT) {
                uint32_t off0 = (uint32_t)(nxt * 1024 + j0 * 4 + b_g) * 4u;
                uint32_t off1 = off0 + 16u;
#pragma unroll
                for (int r8 = 0; r8 < CSZ; r8++) {
                    uint32_t mb = (nxt ? rmb1[r8] : rmb0[r8]);
                    st_async_f32(rdata[r8] + off0, h_new0, mb);
                    st_async_f32(rdata[r8] + off1, h_new1, mb);
                }
            }
        }

        // -- xi warps: stage xs[t+3] + compute xiF[t+2] in the slack --
        if (tid >= 128) {
            int sb = u & 3, skk = u >> 2;
            float4 v0, v1;
            bool do_stage = (t + 3 < TT);
            if (do_stage) {
                const float* src = xs + ((size_t)(t + 3) * 64 + cid * 4 + sb) * 256 + skk * 8;
                v0 = __ldg((const float4*)src);
                v1 = __ldg((const float4*)(src + 4));
            }
            if (t + 2 < TT)
                xi_compute(sm, u, (t + 2) & 3, (t + 2) & 3);
            if (do_stage) {
                float* dst = sm + OFF_XS + ((t + 3) & 3) * 2048;
                int k0 = skk * 8;
                *(unsigned long long*)(dst + (k0 + 0) * 8 + sb * 2) = dup2(v0.x);
                *(unsigned long long*)(dst + (k0 + 1) * 8 + sb * 2) = dup2(v0.y);
                *(unsigned long long*)(dst + (k0 + 2) * 8 + sb * 2) = dup2(v0.z);
                *(unsigned long long*)(dst + (k0 + 3) * 8 + sb * 2) = dup2(v0.w);
                *(unsigned long long*)(dst + (k0 + 4) * 8 + sb * 2) = dup2(v1.x);
                *(unsigned long long*)(dst + (k0 + 5) * 8 + sb * 2) = dup2(v1.y);
                *(unsigned long long*)(dst + (k0 + 6) * 8 + sb * 2) = dup2(v1.z);
                *(unsigned long long*)(dst + (k0 + 7) * 8 + sb * 2) = dup2(v1.w);
            }
        }

        if (t + 1 < TT) {
            // wait for all 8 CTAs' h_new bytes for buffer nxt (cta-scope acquire)
            if (nxt) { mbar_wait_cta(mbase + 8u, ph1); ph1 ^= 1; }
            else     { mbar_wait_cta(mbase,      ph0); ph0 ^= 1; }
        }
        cur = nxt;
    }

    // no CTA exits while peers might still reference its smem
    asm volatile("barrier.cluster.arrive.aligned;" ::: "memory");
    asm volatile("barrier.cluster.wait.aligned;" ::: "memory");
}

// ============================================================
extern "C" void kernel_launch(void* const* d_in, const int* in_sizes, int n_in,
                              void* d_out, int out_size) {
    const float* c    = (const float*)d_in[0];
    const float* xs   = (const float*)d_in[1];
    const float* Wi   = (const float*)d_in[2];
    const float* Wh   = (const float*)d_in[3];
    const float* bh   = (const float*)d_in[4];
    const float* b_in = (const float*)d_in[5];

    float* dmp;
    cudaGetSymbolAddress((void**)&dmp, g_dump);

    float* out = (float*)d_out;
    float* finalc;
    float* ys;
    const long long full = (long long)BB * HH + (long long)TT * BB * HH;
    if ((long long)out_size >= full) {
        finalc = out;            // tuple order: final_c first, then ys
        ys = out + BB * HH;
    } else if ((long long)out_size >= (long long)TT * BB * HH) {
        ys = out;
        finalc = dmp;
    } else {
        finalc = out;
        ys = dmp;
    }

    // REQUIRED: smem > 48KB default limit
    cudaFuncSetAttribute(gru_rec_kernel, cudaFuncAttributeMaxDynamicSharedMemorySize, SMEM_BYTES);

    // single fused kernel: recurrence + in-slack xi production
    gru_rec_kernel<<<NCTA, NT, SMEM_BYTES>>>(c, xs, Wi, Wh, bh, b_in, ys, finalc);
}

// round 15
// speedup vs baseline: 2.1235x; 2.1235x over previous
#include <cuda_runtime.h>
#include <cuda_bf16.h>
#include <cstdint>

// Problem dims
#define TT 2048
#define BB 64
#define FFD 256
#define HH 256
#define NG 768  // 3*H

// Recurrence config: 32 clusters x 4 CTAs, 256 threads
#define CSZ 4
#define NCTA 128
#define NT 256

// -------- device scratch --------
__device__ float g_xi[(size_t)TT * BB * NG];     // 2048*64*768
__device__ float g_dump[(size_t)TT * BB * HH];   // fallback ys sink

// -------- packed f32x2 helpers --------
__device__ __forceinline__ void ffma2(unsigned long long& d, unsigned long long a, unsigned long long b) {
    asm volatile("fma.rn.f32x2 %0, %1, %2, %0;" : "+l"(d) : "l"(a), "l"(b));
}
__device__ __forceinline__ unsigned long long dup2(float a) {
    unsigned long long d;
    asm("mov.b64 %0, {%1, %1};" : "=l"(d) : "f"(a));
    return d;
}
__device__ __forceinline__ unsigned long long pack2(float a, float b) {
    unsigned long long d;
    asm("mov.b64 %0, {%1, %2};" : "=l"(d) : "f"(a), "f"(b));
    return d;
}
__device__ __forceinline__ float2 unpack2(unsigned long long d) {
    float2 f;
    asm("mov.b64 {%0, %1}, %2;" : "=f"(f.x), "=f"(f.y) : "l"(d));
    return f;
}
__device__ __forceinline__ float tanh_ap(float x) {
    float y;
    asm("tanh.approx.f32 %0, %1;" : "=f"(y) : "f"(x));
    return y;
}
__device__ __forceinline__ float sigmoid_ap(float x) {
    return 0.5f * tanh_ap(0.5f * x) + 0.5f;
}
__device__ __forceinline__ uint32_t smem_u32(const void* p) {
    uint32_t a;
    asm("{ .reg .u64 t; cvta.to.shared.u64 t, %1; cvt.u32.u64 %0, t; }" : "=r"(a) : "l"(p));
    return a;
}
// CTA-scope wait: no cluster-scope acquire -> no CCTL.IVALL on the poll loop.
__device__ __forceinline__ void mbar_wait_cta(uint32_t mbar, unsigned parity) {
    asm volatile(
        "{\n\t.reg .pred p;\n\t"
        "WAIT_%=:\n\t"
        "mbarrier.try_wait.parity.acquire.cta.shared::cta.b64 p, [%0], %1, 0x989680;\n\t"
        "@!p bra WAIT_%=;\n\t}"
        :: "r"(mbar), "r"(parity) : "memory");
}
// Remote tx-tracked 8B store (dup'd f32 pair) to peer CTA smem.
__device__ __forceinline__ void st_async_u64(uint32_t daddr, unsigned long long v, uint32_t maddr) {
    asm volatile(
        "st.async.shared::cluster.mbarrier::complete_tx::bytes.b64 [%0], %1, [%2];"
        :: "r"(daddr), "l"(v), "r"(maddr) : "memory");
}

// ============================================================
// Kernel 1: xi = xs @ Wi   (M=131072, K=256, N=768) — FFMA2 tiled
// ============================================================
__global__ __launch_bounds__(256, 2) void gemm_xi_kernel(const float* __restrict__ A,
                                                         const float* __restrict__ W) {
    __shared__ float As[16][132];
    __shared__ float Bs[16][128];
    const int tid = threadIdx.x;
    const int m0 = blockIdx.y * 128;
    const int n0 = blockIdx.x * 128;
    const int nt = tid & 15;
    const int mt = tid >> 4;

    unsigned long long acc[8][4];
#pragma unroll
    for (int i = 0; i < 8; i++)
#pragma unroll
        for (int j = 0; j < 4; j++) acc[i][j] = 0ULL;

    for (int kt = 0; kt < 256; kt += 16) {
#pragma unroll
        for (int i = 0; i < 2; i++) {
            int f4 = tid + i * 256;
            int row = f4 >> 2;
            int kq = (f4 & 3) << 2;
            float4 v = *(const float4*)(A + (size_t)(m0 + row) * 256 + kt + kq);
            As[kq + 0][row] = v.x; As[kq + 1][row] = v.y;
            As[kq + 2][row] = v.z; As[kq + 3][row] = v.w;
        }
#pragma unroll
        for (int i = 0; i < 2; i++) {
            int f4 = tid + i * 256;
            int row = f4 >> 5;
            int nq = (f4 & 31) << 2;
            float4 v = *(const float4*)(W + (size_t)(kt + row) * 768 + n0 + nq);
            *(float4*)&Bs[row][nq] = v;
        }
        __syncthreads();
#pragma unroll
        for (int k = 0; k < 16; k++) {
            float4 a0 = *(const float4*)&As[k][mt * 8];
            float4 a1 = *(const float4*)&As[k][mt * 8 + 4];
            ulonglong2 bA = *(const ulonglong2*)&Bs[k][nt * 8];
            ulonglong2 bB = *(const ulonglong2*)&Bs[k][nt * 8 + 4];
            float av[8] = {a0.x, a0.y, a0.z, a0.w, a1.x, a1.y, a1.z, a1.w};
#pragma unroll
            for (int i = 0; i < 8; i++) {
                unsigned long long ad = dup2(av[i]);
                ffma2(acc[i][0], ad, bA.x);
                ffma2(acc[i][1], ad, bA.y);
                ffma2(acc[i][2], ad, bB.x);
                ffma2(acc[i][3], ad, bB.y);
            }
        }
        __syncthreads();
    }
#pragma unroll
    for (int i = 0; i < 8; i++) {
        float2 c0 = unpack2(acc[i][0]);
        float2 c1 = unpack2(acc[i][1]);
        float2 c2 = unpack2(acc[i][2]);
        float2 c3 = unpack2(acc[i][3]);
        size_t off = (size_t)(m0 + mt * 8 + i) * 768 + n0 + nt * 8;
        *(float4*)(g_xi + off)     = make_float4(c0.x, c0.y, c1.x, c1.y);
        *(float4*)(g_xi + off + 4) = make_float4(c2.x, c2.y, c3.x, c3.y);
    }
}

// ============================================================
// Kernel 2: clustered GRU recurrence — CSZ=4 (halved comm scale)
// 32 clusters x 4 CTAs; cluster owns 2 batches; rank owns 64 j-cols
// (192 Wh cols in 96 f32x2 REGISTERS per thread).
// h dup'd f32x2 in smem; exchange = st.async.b64 x 4 ranks (512 msgs/CTA);
// R7's monolithic mbarrier expect_tx/acquire.cta ping-pong, unchanged.
// ============================================================

// smem float offsets
#define OFF_RED 0        // [256 threads][14] partials -> 3584
#define OFF_HT  3584     // [2][256 k][2 b] dup'd ull = 1024 ull = 2048 floats
#define OFF_MB  5632     // 2 mbarriers (2 x u64) = 4 floats
#define SMEM_FLOATS 5636
#define SMEM_BYTES (SMEM_FLOATS * 4)   // 22544 B

#define TX_BYTES 4096u   // 4 ranks x 128 values x 8B into each CTA per step

__global__ __launch_bounds__(NT, 1) __cluster_dims__(CSZ, 1, 1)
void gru_rec_kernel(const float* __restrict__ c,
                    const float* __restrict__ Wh,
                    const float* __restrict__ bh,
                    const float* __restrict__ b_in,
                    float* __restrict__ ys,
                    float* __restrict__ finalc) {
    extern __shared__ float sm[];
    float* sRED = sm + OFF_RED;
    float* sHT  = sm + OFF_HT;   // ull slot (buf,k,b) at ull idx buf*512 + k*2 + b

    const int tid = threadIdx.x;
    uint32_t rank;
    asm("mov.u32 %0, %%cluster_ctarank;" : "=r"(rank));
    const int cid = blockIdx.x >> 2;          // cluster id 0..31 (batches 2cid, 2cid+1)

    const uint32_t mbase = smem_u32(sm + OFF_MB);   // mbar[buf] at mbase + buf*8

    // ---- init mbarriers (count = 1: the local expect_tx arrival) ----
    if (tid == 0) {
        asm volatile("mbarrier.init.shared.b64 [%0], %1;" :: "r"(mbase), "r"(1u) : "memory");
        asm volatile("mbarrier.init.shared.b64 [%0], %1;" :: "r"(mbase + 8), "r"(1u) : "memory");
        // expect for the FIRST exchange (step 0 writes buffer 1 via mb[1])
        asm volatile("mbarrier.arrive.expect_tx.shared.b64 _, [%0], %1;"
                     :: "r"(mbase + 8), "r"(TX_BYTES) : "memory");
    }

    // ---- phase-1 mapping + weight load into registers ----
    const int kc = tid >> 5;       // k-chunk 0..7 (32 k each)
    const int jp = tid & 31;       // j-pair 0..31 -> global j (rank*64 + 2jp, +1)
    const int j0w = (int)rank * 64 + jp * 2;

    unsigned long long wreg[96];   // [kk 0..31][g 0..2] f32x2 over j-pair
#pragma unroll
    for (int kk = 0; kk < 32; kk++) {
#pragma unroll
        for (int g = 0; g < 3; g++) {
            float2 w2 = __ldg((const float2*)(Wh + (size_t)(kc * 32 + kk) * 768 + g * 256 + j0w));
            wreg[kk * 3 + g] = pack2(w2.x, w2.y);
        }
    }

    // initial h (dup'd) into buf 0: slot (0,k,b) = c[cid*2+b][k]
    for (int idx = tid; idx < 512; idx += NT) {
        int k = idx >> 1;
        int b = idx & 1;
        float v = __ldg(c + (size_t)(cid * 2 + b) * 256 + k);
        *((unsigned long long*)sHT + (k * 2 + b)) = dup2(v);
    }

    // gate mapping (tid < 128): one (j, b) per thread
    const int jl = tid & 63;                     // j within rank slice
    const int b_g = (tid >> 6) & 1;              // batch 0..1
    const int j0 = (int)rank * 64 + jl;          // global j
    const int b_glob = cid * 2 + b_g;
    const int jpr = jl >> 1;                     // producer j-pair
    const int half = jl & 1;                     // lane within pair

    float bhr = 0.f, bhz = 0.f, bhn = 0.f, bin = 0.f;
    if (tid < 128) {
        bhr = __ldg(bh + j0);
        bhz = __ldg(bh + 256 + j0);
        bhn = __ldg(bh + 512 + j0);
        bin = __ldg(b_in + j0);
    }

    // remote addresses for all 4 ranks (incl self)
    uint32_t ht_local = smem_u32(sHT);
    uint32_t rdata[CSZ], rmb0[CSZ], rmb1[CSZ];
#pragma unroll
    for (int r = 0; r < CSZ; r++) {
        asm("mapa.shared::cluster.u32 %0, %1, %2;" : "=r"(rdata[r]) : "r"(ht_local), "r"(r));
        asm("mapa.shared::cluster.u32 %0, %1, %2;" : "=r"(rmb0[r]) : "r"(mbase), "r"(r));
        asm("mapa.shared::cluster.u32 %0, %1, %2;" : "=r"(rmb1[r]) : "r"(mbase + 8u), "r"(r));
    }

    __syncthreads();
    // ONE-TIME: mbarriers + buf0 ready everywhere before any peer traffic
    asm volatile("barrier.cluster.arrive.aligned;" ::: "memory");
    asm volatile("barrier.cluster.wait.aligned;" ::: "memory");

    // prefetch xi for t=0
    float xr = 0.f, xz = 0.f, xn = 0.f;
    if (tid < 128) {
        const float* xp = g_xi + (size_t)b_glob * 768 + j0;
        xr = __ldg(xp);
        xz = __ldg(xp + 256);
        xn = __ldg(xp + 512);
    }

    unsigned ph0 = 0, ph1 = 0;   // parity trackers for mb[0], mb[1]
    int cur = 0;
    for (int t = 0; t < TT; t++) {
        const int nxt = cur ^ 1;

        // -- phase 1: register-weight GEMV partials (dup'd h, no MOVs) --
        unsigned long long acc[3][2];
#pragma unroll
        for (int g = 0; g < 3; g++) {
            acc[g][0] = 0ULL;
            acc[g][1] = 0ULL;
        }
        {
            const unsigned long long* hb =
                (const unsigned long long*)sHT + cur * 512 + kc * 64;  // 32 k x 2 slots
#pragma unroll
            for (int kk = 0; kk < 32; kk++) {
                ulonglong2 h2 = *(const ulonglong2*)(hb + kk * 2);  // dup(b0), dup(b1)
                unsigned long long w0 = wreg[kk * 3 + 0];
                unsigned long long w1 = wreg[kk * 3 + 1];
                unsigned long long w2 = wreg[kk * 3 + 2];
                ffma2(acc[0][0], w0, h2.x); ffma2(acc[0][1], w0, h2.y);
                ffma2(acc[1][0], w1, h2.x); ffma2(acc[1][1], w1, h2.y);
                ffma2(acc[2][0], w2, h2.x); ffma2(acc[2][1], w2, h2.y);
            }
        }
        // write partials: per thread 12 floats: [b][g] f32x2
        {
            float* rp = sRED + tid * 14;
#pragma unroll
            for (int b = 0; b < 2; b++) {
                *(unsigned long long*)(rp + b * 6 + 0) = acc[0][b];
                *(unsigned long long*)(rp + b * 6 + 2) = acc[1][b];
                *(unsigned long long*)(rp + b * 6 + 4) = acc[2][b];
            }
        }
        __syncthreads();   // sync1

        // post expect_tx for the exchange at step t+1 (uses mb[cur])
        if (tid == 128 && t + 2 < TT) {
            uint32_t mb = mbase + (uint32_t)cur * 8u;
            asm volatile("mbarrier.arrive.expect_tx.shared.b64 _, [%0], %1;"
                         :: "r"(mb), "r"(TX_BYTES) : "memory");
        }

        // -- phase 2+3: reduce + gates + direct sends (128 threads) --
        if (tid < 128) {
            float hr = 0.f, hz = 0.f, hn = 0.f;
            const float* rp0 = sRED + jpr * 14 + b_g * 6 + half;
#pragma unroll
            for (int q = 0; q < 8; q++) {
                const float* pq = rp0 + q * (32 * 14);
                hr += pq[0];
                hz += pq[2];
                hn += pq[4];
            }
            float h_old = sHT[(cur * 512 + j0 * 2 + b_g) * 2];
            float r = sigmoid_ap(xr + hr + bhr);
            float z = sigmoid_ap(xz + hz + bhz);
            float n = tanh_ap(xn + bin + r * (hn + bhn));
            float h_new = (1.0f - z) * n + z * h_old;

            ys[((size_t)t * 64 + b_glob) * 256 + j0] = h_new;
            if (t == TT - 1)
                finalc[(size_t)b_glob * 256 + j0] = h_new;

            if (t + 1 < TT) {
                unsigned long long hv = dup2(h_new);
                uint32_t doff = (uint32_t)(nxt * 512 + j0 * 2 + b_g) * 8u;
#pragma unroll
                for (int r4 = 0; r4 < CSZ; r4++) {
                    uint32_t mb = (nxt ? rmb1[r4] : rmb0[r4]);
                    st_async_u64(rdata[r4] + doff, hv, mb);
                }
            }
            // prefetch xi for t+1 before blocking
            if (t + 1 < TT) {
                const float* xp = g_xi + ((size_t)(t + 1) * 64 + b_glob) * 768 + j0;
                xr = __ldg(xp);
                xz = __ldg(xp + 256);
                xn = __ldg(xp + 512);
            }
        }

        if (t + 1 < TT) {
            // wait for all 4 CTAs' h_new bytes for buffer nxt (cta-scope acquire)
            if (nxt) { mbar_wait_cta(mbase + 8u, ph1); ph1 ^= 1; }
            else     { mbar_wait_cta(mbase,      ph0); ph0 ^= 1; }
        }
        cur = nxt;
    }

    // no CTA exits while peers might still write its smem
    asm volatile("barrier.cluster.arrive.aligned;" ::: "memory");
    asm volatile("barrier.cluster.wait.aligned;" ::: "memory");
}

// ============================================================
extern "C" void kernel_launch(void* const* d_in, const int* in_sizes, int n_in,
                              void* d_out, int out_size) {
    const float* c    = (const float*)d_in[0];
    const float* xs   = (const float*)d_in[1];
    const float* Wi   = (const float*)d_in[2];
    const float* Wh   = (const float*)d_in[3];
    const float* bh   = (const float*)d_in[4];
    const float* b_in = (const float*)d_in[5];

    float* dmp;
    cudaGetSymbolAddress((void**)&dmp, g_dump);

    float* out = (float*)d_out;
    float* finalc;
    float* ys;
    const long long full = (long long)BB * HH + (long long)TT * BB * HH;
    if ((long long)out_size >= full) {
        finalc = out;            // tuple order: final_c first, then ys
        ys = out + BB * HH;
    } else if ((long long)out_size >= (long long)TT * BB * HH) {
        ys = out;
        finalc = dmp;
    } else {
        finalc = out;
        ys = dmp;
    }

    // smem attr (harmless when under 48KB; mandatory habit after R9/R10)
    cudaFuncSetAttribute(gru_rec_kernel, cudaFuncAttributeMaxDynamicSharedMemorySize, SMEM_BYTES);

    // 1) xi = xs @ Wi
    dim3 ggrid(NG / 128, (TT * BB) / 128);
    gemm_xi_kernel<<<ggrid, 256>>>(xs, Wi);
    // 2) clustered recurrence (CSZ=4)
    gru_rec_kernel<<<NCTA, NT, SMEM_BYTES>>>(c, Wh, bh, b_in, ys, finalc);
}

// round 16
// speedup vs baseline: 2.1442x; 1.0098x over previous
#include <cuda_runtime.h>
#include <cuda_bf16.h>
#include <cstdint>

// Problem dims
#define TT 2048
#define BB 64
#define FFD 256
#define HH 256
#define NG 768  // 3*H

// Recurrence config: 32 clusters x 4 CTAs, 256 threads
#define CSZ 4
#define NCTA 128
#define NT 256

// -------- device scratch --------
__device__ float g_xi[(size_t)TT * BB * NG];     // 2048*64*768
__device__ float g_dump[(size_t)TT * BB * HH];   // fallback ys sink

// -------- packed f32x2 helpers --------
__device__ __forceinline__ void ffma2(unsigned long long& d, unsigned long long a, unsigned long long b) {
    asm volatile("fma.rn.f32x2 %0, %1, %2, %0;" : "+l"(d) : "l"(a), "l"(b));
}
__device__ __forceinline__ unsigned long long dup2(float a) {
    unsigned long long d;
    asm("mov.b64 %0, {%1, %1};" : "=l"(d) : "f"(a));
    return d;
}
__device__ __forceinline__ unsigned long long pack2(float a, float b) {
    unsigned long long d;
    asm("mov.b64 %0, {%1, %2};" : "=l"(d) : "f"(a), "f"(b));
    return d;
}
__device__ __forceinline__ float2 unpack2(unsigned long long d) {
    float2 f;
    asm("mov.b64 {%0, %1}, %2;" : "=f"(f.x), "=f"(f.y) : "l"(d));
    return f;
}
__device__ __forceinline__ float tanh_ap(float x) {
    float y;
    asm("tanh.approx.f32 %0, %1;" : "=f"(y) : "f"(x));
    return y;
}
__device__ __forceinline__ float sigmoid_ap(float x) {
    return 0.5f * tanh_ap(0.5f * x) + 0.5f;
}
__device__ __forceinline__ uint32_t smem_u32(const void* p) {
    uint32_t a;
    asm("{ .reg .u64 t; cvta.to.shared.u64 t, %1; cvt.u32.u64 %0, t; }" : "=r"(a) : "l"(p));
    return a;
}
// CTA-scope wait: no cluster-scope acquire -> no CCTL.IVALL on the poll loop.
__device__ __forceinline__ void mbar_wait_cta(uint32_t mbar, unsigned parity) {
    asm volatile(
        "{\n\t.reg .pred p;\n\t"
        "WAIT_%=:\n\t"
        "mbarrier.try_wait.parity.acquire.cta.shared::cta.b64 p, [%0], %1, 0x989680;\n\t"
        "@!p bra WAIT_%=;\n\t}"
        :: "r"(mbar), "r"(parity) : "memory");
}
// Remote tx-tracked 8B store (dup'd f32 pair) to peer CTA smem.
__device__ __forceinline__ void st_async_u64(uint32_t daddr, unsigned long long v, uint32_t maddr) {
    asm volatile(
        "st.async.shared::cluster.mbarrier::complete_tx::bytes.b64 [%0], %1, [%2];"
        :: "r"(daddr), "l"(v), "r"(maddr) : "memory");
}

// ============================================================
// Kernel 1: xi = xs @ Wi (M=131072, K=256, N=768)
// Double-buffered smem ping-pong, register prefetch, 1 sync/iter.
// ============================================================
__global__ __launch_bounds__(256, 2) void gemm_xi_kernel(const float* __restrict__ A,
                                                         const float* __restrict__ W) {
    __shared__ float As[2][16][132];
    __shared__ float Bs[2][16][128];
    const int tid = threadIdx.x;
    const int m0 = blockIdx.y * 128;
    const int n0 = blockIdx.x * 128;
    const int nt = tid & 15;
    const int mt = tid >> 4;

    // loader indices (computed once)
    const int af0 = tid;             // A frag 0: row, kq
    const int af1 = tid + 256;
    const int arow0 = af0 >> 2, akq0 = (af0 & 3) << 2;
    const int arow1 = af1 >> 2, akq1 = (af1 & 3) << 2;
    const int brow0 = af0 >> 5, bnq0 = (af0 & 31) << 2;
    const int brow1 = af1 >> 5, bnq1 = (af1 & 31) << 2;

    unsigned long long acc[8][4];
#pragma unroll
    for (int i = 0; i < 8; i++)
#pragma unroll
        for (int j = 0; j < 4; j++) acc[i][j] = 0ULL;

    // prefetch tile kt=0 into registers
    float4 ra0 = *(const float4*)(A + (size_t)(m0 + arow0) * 256 + 0 + akq0);
    float4 ra1 = *(const float4*)(A + (size_t)(m0 + arow1) * 256 + 0 + akq1);
    float4 rb0 = *(const float4*)(W + (size_t)(0 + brow0) * 768 + n0 + bnq0);
    float4 rb1 = *(const float4*)(W + (size_t)(0 + brow1) * 768 + n0 + bnq1);

#pragma unroll 1
    for (int kti = 0; kti < 16; kti++) {
        const int p = kti & 1;
        // store current regs into buffer p
        As[p][akq0 + 0][arow0] = ra0.x; As[p][akq0 + 1][arow0] = ra0.y;
        As[p][akq0 + 2][arow0] = ra0.z; As[p][akq0 + 3][arow0] = ra0.w;
        As[p][akq1 + 0][arow1] = ra1.x; As[p][akq1 + 1][arow1] = ra1.y;
        As[p][akq1 + 2][arow1] = ra1.z; As[p][akq1 + 3][arow1] = ra1.w;
        *(float4*)&Bs[p][brow0][bnq0] = rb0;
        *(float4*)&Bs[p][brow1][bnq1] = rb1;
        __syncthreads();

        // prefetch next tile while computing
        if (kti < 15) {
            const int kt = (kti + 1) * 16;
            ra0 = *(const float4*)(A + (size_t)(m0 + arow0) * 256 + kt + akq0);
            ra1 = *(const float4*)(A + (size_t)(m0 + arow1) * 256 + kt + akq1);
            rb0 = *(const float4*)(W + (size_t)(kt + brow0) * 768 + n0 + bnq0);
            rb1 = *(const float4*)(W + (size_t)(kt + brow1) * 768 + n0 + bnq1);
        }

#pragma unroll
        for (int k = 0; k < 16; k++) {
            float4 a0 = *(const float4*)&As[p][k][mt * 8];
            float4 a1 = *(const float4*)&As[p][k][mt * 8 + 4];
            ulonglong2 bA = *(const ulonglong2*)&Bs[p][k][nt * 8];
            ulonglong2 bB = *(const ulonglong2*)&Bs[p][k][nt * 8 + 4];
            float av[8] = {a0.x, a0.y, a0.z, a0.w, a1.x, a1.y, a1.z, a1.w};
#pragma unroll
            for (int i = 0; i < 8; i++) {
                unsigned long long ad = dup2(av[i]);
                ffma2(acc[i][0], ad, bA.x);
                ffma2(acc[i][1], ad, bA.y);
                ffma2(acc[i][2], ad, bB.x);
                ffma2(acc[i][3], ad, bB.y);
            }
        }
        // next iteration's STS targets the other buffer; its previous readers
        // finished before the sync above -> no second barrier needed
    }

#pragma unroll
    for (int i = 0; i < 8; i++) {
        float2 c0 = unpack2(acc[i][0]);
        float2 c1 = unpack2(acc[i][1]);
        float2 c2 = unpack2(acc[i][2]);
        float2 c3 = unpack2(acc[i][3]);
        size_t off = (size_t)(m0 + mt * 8 + i) * 768 + n0 + nt * 8;
        *(float4*)(g_xi + off)     = make_float4(c0.x, c0.y, c1.x, c1.y);
        *(float4*)(g_xi + off + 4) = make_float4(c2.x, c2.y, c3.x, c3.y);
    }
}

// ============================================================
// Kernel 2: clustered GRU recurrence — CSZ=4 (UNCHANGED from R15 best)
// ============================================================

// smem float offsets
#define OFF_RED 0        // [256 threads][14] partials -> 3584
#define OFF_HT  3584     // [2][256 k][2 b] dup'd ull = 1024 ull = 2048 floats
#define OFF_MB  5632     // 2 mbarriers (2 x u64) = 4 floats
#define SMEM_FLOATS 5636
#define SMEM_BYTES (SMEM_FLOATS * 4)   // 22544 B

#define TX_BYTES 4096u   // 4 ranks x 128 values x 8B into each CTA per step

__global__ __launch_bounds__(NT, 1) __cluster_dims__(CSZ, 1, 1)
void gru_rec_kernel(const float* __restrict__ c,
                    const float* __restrict__ Wh,
                    const float* __restrict__ bh,
                    const float* __restrict__ b_in,
                    float* __restrict__ ys,
                    float* __restrict__ finalc) {
    extern __shared__ float sm[];
    float* sRED = sm + OFF_RED;
    float* sHT  = sm + OFF_HT;   // ull slot (buf,k,b) at ull idx buf*512 + k*2 + b

    const int tid = threadIdx.x;
    uint32_t rank;
    asm("mov.u32 %0, %%cluster_ctarank;" : "=r"(rank));
    const int cid = blockIdx.x >> 2;          // cluster id 0..31 (batches 2cid, 2cid+1)

    const uint32_t mbase = smem_u32(sm + OFF_MB);   // mbar[buf] at mbase + buf*8

    // ---- init mbarriers (count = 1: the local expect_tx arrival) ----
    if (tid == 0) {
        asm volatile("mbarrier.init.shared.b64 [%0], %1;" :: "r"(mbase), "r"(1u) : "memory");
        asm volatile("mbarrier.init.shared.b64 [%0], %1;" :: "r"(mbase + 8), "r"(1u) : "memory");
        // expect for the FIRST exchange (step 0 writes buffer 1 via mb[1])
        asm volatile("mbarrier.arrive.expect_tx.shared.b64 _, [%0], %1;"
                     :: "r"(mbase + 8), "r"(TX_BYTES) : "memory");
    }

    // ---- phase-1 mapping + weight load into registers ----
    const int kc = tid >> 5;       // k-chunk 0..7 (32 k each)
    const int jp = tid & 31;       // j-pair 0..31 -> global j (rank*64 + 2jp, +1)
    const int j0w = (int)rank * 64 + jp * 2;

    unsigned long long wreg[96];   // [kk 0..31][g 0..2] f32x2 over j-pair
#pragma unroll
    for (int kk = 0; kk < 32; kk++) {
#pragma unroll
        for (int g = 0; g < 3; g++) {
            float2 w2 = __ldg((const float2*)(Wh + (size_t)(kc * 32 + kk) * 768 + g * 256 + j0w));
            wreg[kk * 3 + g] = pack2(w2.x, w2.y);
        }
    }

    // initial h (dup'd) into buf 0: slot (0,k,b) = c[cid*2+b][k]
    for (int idx = tid; idx < 512; idx += NT) {
        int k = idx >> 1;
        int b = idx & 1;
        float v = __ldg(c + (size_t)(cid * 2 + b) * 256 + k);
        *((unsigned long long*)sHT + (k * 2 + b)) = dup2(v);
    }

    // gate mapping (tid < 128): one (j, b) per thread
    const int jl = tid & 63;                     // j within rank slice
    const int b_g = (tid >> 6) & 1;              // batch 0..1
    const int j0 = (int)rank * 64 + jl;          // global j
    const int b_glob = cid * 2 + b_g;
    const int jpr = jl >> 1;                     // producer j-pair
    const int half = jl & 1;                     // lane within pair

    float bhr = 0.f, bhz = 0.f, bhn = 0.f, bin = 0.f;
    if (tid < 128) {
        bhr = __ldg(bh + j0);
        bhz = __ldg(bh + 256 + j0);
        bhn = __ldg(bh + 512 + j0);
        bin = __ldg(b_in + j0);
    }

    // remote addresses for all 4 ranks (incl self)
    uint32_t ht_local = smem_u32(sHT);
    uint32_t rdata[CSZ], rmb0[CSZ], rmb1[CSZ];
#pragma unroll
    for (int r = 0; r < CSZ; r++) {
        asm("mapa.shared::cluster.u32 %0, %1, %2;" : "=r"(rdata[r]) : "r"(ht_local), "r"(r));
        asm("mapa.shared::cluster.u32 %0, %1, %2;" : "=r"(rmb0[r]) : "r"(mbase), "r"(r));
        asm("mapa.shared::cluster.u32 %0, %1, %2;" : "=r"(rmb1[r]) : "r"(mbase + 8u), "r"(r));
    }

    __syncthreads();
    // ONE-TIME: mbarriers + buf0 ready everywhere before any peer traffic
    asm volatile("barrier.cluster.arrive.aligned;" ::: "memory");
    asm volatile("barrier.cluster.wait.aligned;" ::: "memory");

    // prefetch xi for t=0
    float xr = 0.f, xz = 0.f, xn = 0.f;
    if (tid < 128) {
        const float* xp = g_xi + (size_t)b_glob * 768 + j0;
        xr = __ldg(xp);
        xz = __ldg(xp + 256);
        xn = __ldg(xp + 512);
    }

    unsigned ph0 = 0, ph1 = 0;   // parity trackers for mb[0], mb[1]
    int cur = 0;
    for (int t = 0; t < TT; t++) {
        const int nxt = cur ^ 1;

        // -- phase 1: register-weight GEMV partials (dup'd h, no MOVs) --
        unsigned long long acc[3][2];
#pragma unroll
        for (int g = 0; g < 3; g++) {
            acc[g][0] = 0ULL;
            acc[g][1] = 0ULL;
        }
        {
            const unsigned long long* hb =
                (const unsigned long long*)sHT + cur * 512 + kc * 64;  // 32 k x 2 slots
#pragma unroll
            for (int kk = 0; kk < 32; kk++) {
                ulonglong2 h2 = *(const ulonglong2*)(hb + kk * 2);  // dup(b0), dup(b1)
                unsigned long long w0 = wreg[kk * 3 + 0];
                unsigned long long w1 = wreg[kk * 3 + 1];
                unsigned long long w2 = wreg[kk * 3 + 2];
                ffma2(acc[0][0], w0, h2.x); ffma2(acc[0][1], w0, h2.y);
                ffma2(acc[1][0], w1, h2.x); ffma2(acc[1][1], w1, h2.y);
                ffma2(acc[2][0], w2, h2.x); ffma2(acc[2][1], w2, h2.y);
            }
        }
        // write partials: per thread 12 floats: [b][g] f32x2
        {
            float* rp = sRED + tid * 14;
#pragma unroll
            for (int b = 0; b < 2; b++) {
                *(unsigned long long*)(rp + b * 6 + 0) = acc[0][b];
                *(unsigned long long*)(rp + b * 6 + 2) = acc[1][b];
                *(unsigned long long*)(rp + b * 6 + 4) = acc[2][b];
            }
        }
        __syncthreads();   // sync1

        // post expect_tx for the exchange at step t+1 (uses mb[cur])
        if (tid == 128 && t + 2 < TT) {
            uint32_t mb = mbase + (uint32_t)cur * 8u;
            asm volatile("mbarrier.arrive.expect_tx.shared.b64 _, [%0], %1;"
                         :: "r"(mb), "r"(TX_BYTES) : "memory");
        }

        // -- phase 2+3: reduce + gates + direct sends (128 threads) --
        if (tid < 128) {
            float hr = 0.f, hz = 0.f, hn = 0.f;
            const float* rp0 = sRED + jpr * 14 + b_g * 6 + half;
#pragma unroll
            for (int q = 0; q < 8; q++) {
                const float* pq = rp0 + q * (32 * 14);
                hr += pq[0];
                hz += pq[2];
                hn += pq[4];
            }
            float h_old = sHT[(cur * 512 + j0 * 2 + b_g) * 2];
            float r = sigmoid_ap(xr + hr + bhr);
            float z = sigmoid_ap(xz + hz + bhz);
            float n = tanh_ap(xn + bin + r * (hn + bhn));
            float h_new = (1.0f - z) * n + z * h_old;

            ys[((size_t)t * 64 + b_glob) * 256 + j0] = h_new;
            if (t == TT - 1)
                finalc[(size_t)b_glob * 256 + j0] = h_new;

            if (t + 1 < TT) {
                unsigned long long hv = dup2(h_new);
                uint32_t doff = (uint32_t)(nxt * 512 + j0 * 2 + b_g) * 8u;
#pragma unroll
                for (int r4 = 0; r4 < CSZ; r4++) {
                    uint32_t mb = (nxt ? rmb1[r4] : rmb0[r4]);
                    st_async_u64(rdata[r4] + doff, hv, mb);
                }
            }
            // prefetch xi for t+1 before blocking
            if (t + 1 < TT) {
                const float* xp = g_xi + ((size_t)(t + 1) * 64 + b_glob) * 768 + j0;
                xr = __ldg(xp);
                xz = __ldg(xp + 256);
                xn = __ldg(xp + 512);
            }
        }

        if (t + 1 < TT) {
            // wait for all 4 CTAs' h_new bytes for buffer nxt (cta-scope acquire)
            if (nxt) { mbar_wait_cta(mbase + 8u, ph1); ph1 ^= 1; }
            else     { mbar_wait_cta(mbase,      ph0); ph0 ^= 1; }
        }
        cur = nxt;
    }

    // no CTA exits while peers might still write its smem
    asm volatile("barrier.cluster.arrive.aligned;" ::: "memory");
    asm volatile("barrier.cluster.wait.aligned;" ::: "memory");
}

// ============================================================
extern "C" void kernel_launch(void* const* d_in, const int* in_sizes, int n_in,
                              void* d_out, int out_size) {
    const float* c    = (const float*)d_in[0];
    const float* xs   = (const float*)d_in[1];
    const float* Wi   = (const float*)d_in[2];
    const float* Wh   = (const float*)d_in[3];
    const float* bh   = (const float*)d_in[4];
    const float* b_in = (const float*)d_in[5];

    float* dmp;
    cudaGetSymbolAddress((void**)&dmp, g_dump);

    float* out = (float*)d_out;
    float* finalc;
    float* ys;
    const long long full = (long long)BB * HH + (long long)TT * BB * HH;
    if ((long long)out_size >= full) {
        finalc = out;            // tuple order: final_c first, then ys
        ys = out + BB * HH;
    } else if ((long long)out_size >= (long long)TT * BB * HH) {
        ys = out;
        finalc = dmp;
    } else {
        finalc = out;
        ys = dmp;
    }

    // smem attr (harmless when under 48KB; mandatory habit after R9/R10)
    cudaFuncSetAttribute(gru_rec_kernel, cudaFuncAttributeMaxDynamicSharedMemorySize, SMEM_BYTES);

    // 1) xi = xs @ Wi (double-buffered)
    dim3 ggrid(NG / 128, (TT * BB) / 128);
    gemm_xi_kernel<<<ggrid, 256>>>(xs, Wi);
    // 2) clustered recurrence (CSZ=4, R15-proven)
    gru_rec_kernel<<<NCTA, NT, SMEM_BYTES>>>(c, Wh, bh, b_in, ys, finalc);
}